// round 1
// baseline (speedup 1.0000x reference)
#include <cuda_runtime.h>
#include <cuda_bf16.h>
#include <math.h>

#define NN 100000
#define NE 3200000
#define FIN 32
#define HD 64
#define NL 4
#define NA 6158
#define NG 64

// ---------------- scratch (device globals; no allocation allowed) -------------
__device__ int   d_flag;              // 1 if inputs are int64, 0 if int32
__device__ int   d_src[NE];
__device__ int   d_dst[NE];
__device__ int   d_batch32[NN];
__device__ int   d_deg[NN];
__device__ int   d_rowptr[NN + 1];
__device__ int   d_cursor[NN];
__device__ int   d_csr[NE];
__device__ float d_invdeg[NN];
__device__ float d_h0[NN * HD];
__device__ float d_h1[NN * HD];
__device__ float d_agg[NN * HD];
__device__ float d_gsum[NG * HD];
__device__ int   d_gcnt[NG];
__device__ int   d_part[256];

// ---------------- dtype detection + conversion --------------------------------
__global__ void k_detect(const void* edge) {
    // int64 little-endian node ids < 2^31 -> every odd 32-bit word is 0.
    const unsigned int* w = (const unsigned int*)edge;
    int zeros = 0;
    for (int i = 0; i < 128; i++) if (w[2 * i + 1] == 0u) zeros++;
    d_flag = (zeros >= 120) ? 1 : 0;
}

__global__ void k_convert_edges(const void* edge) {
    int i = blockIdx.x * blockDim.x + threadIdx.x;
    if (i >= 2 * NE) return;
    int v;
    if (d_flag) v = (int)((const long long*)edge)[i];
    else        v = ((const int*)edge)[i];
    if (i < NE) d_src[i] = v;
    else        d_dst[i - NE] = v;
}

// zero degree + graph accumulators, convert batch ids
__global__ void k_setup(const void* batch) {
    int i = blockIdx.x * blockDim.x + threadIdx.x;
    if (i < NN) {
        d_deg[i] = 0;
        int b;
        if (d_flag) b = (int)((const long long*)batch)[i];
        else        b = ((const int*)batch)[i];
        d_batch32[i] = b;
    }
    if (i < NG) d_gcnt[i] = 0;
    if (i < NG * HD) d_gsum[i] = 0.f;
}

// ---------------- CSR build ----------------------------------------------------
__global__ void k_degree() {
    int e = blockIdx.x * blockDim.x + threadIdx.x;
    if (e >= NE) return;
    atomicAdd(&d_deg[d_dst[e]], 1);
}

__global__ void k_invdeg() {
    int n = blockIdx.x * blockDim.x + threadIdx.x;
    if (n >= NN) return;
    d_invdeg[n] = 1.0f / fmaxf((float)d_deg[n], 1.0f);
}

// block = 256 threads, 4 elements/thread => 1024 elements/block, 98 blocks
__global__ void k_scan_a() {
    __shared__ int ts[256];
    int b = blockIdx.x, t = threadIdx.x;
    int base = b * 1024 + t * 4;
    int v[4];
    int s = 0;
#pragma unroll
    for (int j = 0; j < 4; j++) {
        int idx = base + j;
        v[j] = (idx < NN) ? d_deg[idx] : 0;
        s += v[j];
    }
    ts[t] = s;
    __syncthreads();
    for (int off = 1; off < 256; off <<= 1) {
        int x = (t >= off) ? ts[t - off] : 0;
        __syncthreads();
        ts[t] += x;
        __syncthreads();
    }
    int run = ts[t] - s;  // exclusive prefix of this thread within block
#pragma unroll
    for (int j = 0; j < 4; j++) {
        int idx = base + j;
        if (idx < NN) d_rowptr[idx] = run;
        run += v[j];
    }
    if (t == 255) d_part[b] = ts[255];
}

__global__ void k_scan_b() {
    __shared__ int ps[128];
    int t = threadIdx.x;
    int orig = (t < 98) ? d_part[t] : 0;
    ps[t] = orig;
    __syncthreads();
    for (int off = 1; off < 128; off <<= 1) {
        int x = (t >= off) ? ps[t - off] : 0;
        __syncthreads();
        ps[t] += x;
        __syncthreads();
    }
    d_part[t] = ps[t] - orig;  // exclusive
    if (t == 0) d_rowptr[NN] = NE;
}

__global__ void k_scan_c() {
    int i = blockIdx.x * blockDim.x + threadIdx.x;
    if (i >= NN) return;
    int r = d_rowptr[i] + d_part[i >> 10];
    d_rowptr[i] = r;
    d_cursor[i] = r;
}

__global__ void k_scatter() {
    int e = blockIdx.x * blockDim.x + threadIdx.x;
    if (e >= NE) return;
    int dd = d_dst[e];
    int pos = atomicAdd(&d_cursor[dd], 1);
    d_csr[pos] = d_src[e];
}

// ---------------- encoder: h0 = relu(x @ W_enc^T + b_enc) ----------------------
__global__ void k_encoder(const float* __restrict__ x,
                          const float* __restrict__ Wenc,
                          const float* __restrict__ benc) {
    __shared__ float Ws[FIN * HD];  // transposed: Ws[k*HD + j]
    __shared__ float bs[HD];
    int t = threadIdx.x;
    for (int i = t; i < HD * FIN; i += blockDim.x) {
        int j = i / FIN, k = i % FIN;
        Ws[k * HD + j] = Wenc[i];
    }
    if (t < HD) bs[t] = benc[t];
    __syncthreads();
    int idx = blockIdx.x * blockDim.x + t;
    if (idx >= NN * HD) return;
    int n = idx >> 6, j = idx & 63;
    const float* xr = x + n * FIN;
    float acc = bs[j];
#pragma unroll
    for (int k = 0; k < FIN; k += 4) {
        float4 xv = *(const float4*)(xr + k);
        acc += xv.x * Ws[k * HD + j] + xv.y * Ws[(k + 1) * HD + j]
             + xv.z * Ws[(k + 2) * HD + j] + xv.w * Ws[(k + 3) * HD + j];
    }
    d_h0[idx] = fmaxf(acc, 0.f);
}

// ---------------- aggregation: agg[n] = mean_{e: dst=n} h[src[e]] --------------
__global__ void k_aggregate(int sel) {
    const float* h = sel ? d_h1 : d_h0;
    int w = (blockIdx.x * blockDim.x + threadIdx.x) >> 5;
    if (w >= NN) return;
    int lane = threadIdx.x & 31;
    int beg = d_rowptr[w], end = d_rowptr[w + 1];
    const float2* __restrict__ hp = (const float2*)h;
    float ax = 0.f, ay = 0.f;
    int i = beg;
    for (; i + 4 <= end; i += 4) {
        int s0 = d_csr[i], s1 = d_csr[i + 1], s2 = d_csr[i + 2], s3 = d_csr[i + 3];
        float2 v0 = hp[s0 * 32 + lane];
        float2 v1 = hp[s1 * 32 + lane];
        float2 v2 = hp[s2 * 32 + lane];
        float2 v3 = hp[s3 * 32 + lane];
        ax += v0.x + v1.x + v2.x + v3.x;
        ay += v0.y + v1.y + v2.y + v3.y;
    }
    for (; i < end; i++) {
        int s = d_csr[i];
        float2 v = hp[s * 32 + lane];
        ax += v.x; ay += v.y;
    }
    float id = d_invdeg[w];
    ((float2*)d_agg)[w * 32 + lane] = make_float2(ax * id, ay * id);
}

// ---------------- layer GEMM: h_out = relu(agg@Wl^T + bl + h@Wr^T) + h ---------
__global__ void __launch_bounds__(128)
k_layer(int sel,
        const float* __restrict__ Wl, const float* __restrict__ bl,
        const float* __restrict__ Wr) {
    const float* h    = sel ? d_h1 : d_h0;
    float*       hout = sel ? d_h0 : d_h1;
    __shared__ float Wls[HD * HD];  // row-major [j][k]
    __shared__ float Wrs[HD * HD];
    __shared__ float bls[HD];
    int t = threadIdx.x;
    for (int i = t; i < HD * HD; i += 128) { Wls[i] = Wl[i]; Wrs[i] = Wr[i]; }
    if (t < HD) bls[t] = bl[t];
    __syncthreads();
    int n = blockIdx.x * 128 + t;
    if (n >= NN) return;

    float acc[HD];
#pragma unroll
    for (int j = 0; j < HD; j++) acc[j] = 0.f;

    const float4* __restrict__ ar = (const float4*)(d_agg + n * HD);
    const float4* __restrict__ hr = (const float4*)(h + n * HD);
#pragma unroll 2
    for (int k4 = 0; k4 < 16; k4++) {
        float4 a = ar[k4];
        float4 b = hr[k4];
#pragma unroll
        for (int j = 0; j < HD; j++) {
            float4 wl = *(const float4*)(&Wls[j * HD + k4 * 4]);
            float4 wr = *(const float4*)(&Wrs[j * HD + k4 * 4]);
            acc[j] += a.x * wl.x + a.y * wl.y + a.z * wl.z + a.w * wl.w
                    + b.x * wr.x + b.y * wr.y + b.z * wr.z + b.w * wr.w;
        }
    }
#pragma unroll
    for (int j = 0; j < HD; j += 4) {
        float4 hv = *(const float4*)(h + n * HD + j);
        float4 o;
        o.x = fmaxf(acc[j + 0] + bls[j + 0], 0.f) + hv.x;
        o.y = fmaxf(acc[j + 1] + bls[j + 1], 0.f) + hv.y;
        o.z = fmaxf(acc[j + 2] + bls[j + 2], 0.f) + hv.z;
        o.w = fmaxf(acc[j + 3] + bls[j + 3], 0.f) + hv.w;
        *(float4*)(hout + n * HD + j) = o;
    }
}

// ---------------- global mean pool ---------------------------------------------
__global__ void k_count() {
    int n = blockIdx.x * blockDim.x + threadIdx.x;
    if (n >= NN) return;
    atomicAdd(&d_gcnt[d_batch32[n]], 1);
}

// block = 64 threads (one per column), each block scans 256 sorted nodes
__global__ void k_pool(int sel) {
    const float* h = sel ? d_h1 : d_h0;
    int t = threadIdx.x;
    int n0 = blockIdx.x * 256;
    if (n0 >= NN) return;
    int nend = n0 + 256; if (nend > NN) nend = NN;
    int cur = d_batch32[n0];
    float acc = 0.f;
    for (int n = n0; n < nend; n++) {
        int g = d_batch32[n];
        if (g != cur) {
            atomicAdd(&d_gsum[cur * HD + t], acc);
            acc = 0.f;
            cur = g;
        }
        acc += h[n * HD + t];
    }
    atomicAdd(&d_gsum[cur * HD + t], acc);
}

// ---------------- heads --------------------------------------------------------
__global__ void __launch_bounds__(128)
k_policy(const float* __restrict__ Wp, const float* __restrict__ bp,
         float* __restrict__ out) {
    __shared__ float repr[NG * HD];  // 16 KB
    int t = threadIdx.x;
    for (int i = t; i < NG * HD; i += 128) {
        int g = i >> 6;
        repr[i] = d_gsum[i] / fmaxf((float)d_gcnt[g], 1.f);
    }
    __syncthreads();
    int a = blockIdx.x * 128 + t;
    if (a >= NA) return;
    float acc[NG];
#pragma unroll
    for (int g = 0; g < NG; g++) acc[g] = 0.f;
    const float4* __restrict__ wr = (const float4*)(Wp + a * HD);
#pragma unroll 2
    for (int k4 = 0; k4 < 16; k4++) {
        float4 w = wr[k4];
#pragma unroll
        for (int g = 0; g < NG; g++) {
            float4 r = *(const float4*)(&repr[g * HD + k4 * 4]);
            acc[g] += w.x * r.x + w.y * r.y + w.z * r.z + w.w * r.w;
        }
    }
    float bias = bp[a];
#pragma unroll
    for (int g = 0; g < NG; g++) out[g * NA + a] = acc[g] + bias;
}

__global__ void k_value(const float* __restrict__ Wv,
                        const float* __restrict__ bv,
                        float* __restrict__ out) {
    int g = threadIdx.x;
    if (g >= NG) return;
    float inv = 1.f / fmaxf((float)d_gcnt[g], 1.f);
    float acc = 0.f;
#pragma unroll
    for (int k = 0; k < HD; k++) acc += d_gsum[g * HD + k] * Wv[k];
    out[NG * NA + g] = tanhf(acc * inv + bv[0]);
}

// ---------------- launcher -----------------------------------------------------
extern "C" void kernel_launch(void* const* d_in, const int* in_sizes, int n_in,
                              void* d_out, int out_size) {
    const float* x     = (const float*)d_in[0];
    const void*  edge  = d_in[1];
    const void*  batch = d_in[2];
    const float* Wenc  = (const float*)d_in[3];
    const float* benc  = (const float*)d_in[4];
    const float* Wl    = (const float*)d_in[5];
    const float* bl    = (const float*)d_in[6];
    const float* Wr    = (const float*)d_in[7];
    const float* Wp    = (const float*)d_in[8];
    const float* bp    = (const float*)d_in[9];
    const float* Wv    = (const float*)d_in[10];
    const float* bv    = (const float*)d_in[11];
    float* out = (float*)d_out;

    k_detect<<<1, 1>>>(edge);
    k_convert_edges<<<(2 * NE + 255) / 256, 256>>>(edge);
    k_setup<<<(NN + 255) / 256, 256>>>(batch);
    k_degree<<<(NE + 255) / 256, 256>>>();
    k_invdeg<<<(NN + 255) / 256, 256>>>();
    k_scan_a<<<98, 256>>>();
    k_scan_b<<<1, 128>>>();
    k_scan_c<<<(NN + 255) / 256, 256>>>();
    k_scatter<<<(NE + 255) / 256, 256>>>();

    k_encoder<<<(NN * HD + 255) / 256, 256>>>(x, Wenc, benc);

    int sel = 0;  // current h buffer: 0 -> d_h0
    for (int i = 0; i < NL; i++) {
        k_aggregate<<<(NN * 32 + 255) / 256, 256>>>(sel);
        k_layer<<<(NN + 127) / 128, 128>>>(sel, Wl + i * HD * HD, bl + i * HD,
                                           Wr + i * HD * HD);
        sel ^= 1;
    }

    k_count<<<(NN + 255) / 256, 256>>>();
    k_pool<<<(NN + 255) / 256, 64>>>(sel);
    k_policy<<<(NA + 127) / 128, 128>>>(Wp, bp, out);
    k_value<<<1, 64>>>(Wv, bv, out);
}